// round 1
// baseline (speedup 1.0000x reference)
#include <cuda_runtime.h>
#include <math.h>

// ---------------------------------------------------------------------------
// Problem constants (fixed by the reference)
// ---------------------------------------------------------------------------
#define BATCH   4
#define NTOK    2304          // (96/2)^2
#define DMODEL  256
#define NHEADS  8
#define DK      32
#define DEPTH   3
#define KDROP   345           // int(0.15 * 2304)
#define MTOT    (BATCH * NTOK)   // 9216

// ---------------------------------------------------------------------------
// Scratch (static device globals; no allocation allowed)
// ---------------------------------------------------------------------------
__device__ float g_tokens[MTOT * DMODEL];
__device__ float g_hln   [MTOT * DMODEL];
__device__ float g_qkv   [MTOT * 3 * DMODEL];
__device__ float g_attn  [MTOT * DMODEL];
__device__ float g_mlp   [MTOT * 4 * DMODEL];
__device__ float g_scores[MTOT];
__device__ int   g_mask  [MTOT];

// ---------------------------------------------------------------------------
// Patch embed: tokens[b, n, d] = sum_{c,p,q} x[b,c,2hc+p,2wc+q]*W[d,c,p,q] + pb[d] + pos[n,d]
// ---------------------------------------------------------------------------
__global__ void patch_kernel(const float* __restrict__ x,
                             const float* __restrict__ pw,
                             const float* __restrict__ pb,
                             const float* __restrict__ pos,
                             float* __restrict__ tokens) {
    int t = blockIdx.x;            // 0 .. MTOT-1
    int b = t / NTOK, n = t % NTOK;
    int hc = n / 48, wc = n % 48;
    __shared__ float xs[12];
    if (threadIdx.x < 12) {
        int c = threadIdx.x / 4, pq = threadIdx.x % 4;
        int p = pq / 2, q = pq % 2;
        xs[threadIdx.x] = x[(((size_t)b * 3 + c) * 96 + (hc * 2 + p)) * 96 + (wc * 2 + q)];
    }
    __syncthreads();
    int d = threadIdx.x;
    float acc = pb[d];
#pragma unroll
    for (int e = 0; e < 12; e++) acc = fmaf(xs[e], pw[d * 12 + e], acc);
    tokens[(size_t)t * DMODEL + d] = acc + pos[(size_t)n * DMODEL + d];
}

// ---------------------------------------------------------------------------
// Generic fp32 GEMM: C[M,N] = A[M,K] @ B[K,N] + bias, with epilogue variants.
// 64x64 tile, BK=16, 256 threads, 4x4 microtile.
// ---------------------------------------------------------------------------
enum { EPI_BIAS = 0, EPI_RELU = 1, EPI_GELU = 2, EPI_RES = 3 };

template <int EPI>
__global__ void gemm_kernel(const float* __restrict__ A,
                            const float* __restrict__ Bw,
                            const float* __restrict__ bias,
                            const float* res,          // not restrict: may alias C
                            float* C,                  // not restrict: may alias res
                            int M, int N, int K) {
    __shared__ float As[16][68];
    __shared__ float Bs[16][68];
    int m0 = blockIdx.y * 64, n0 = blockIdx.x * 64;
    int tid = threadIdx.x;
    int tm = (tid >> 4) * 4, tn = (tid & 15) * 4;
    int arow = tid >> 2, ak4 = tid & 3;    // A tile load: 64 rows x 4 float4
    int bk = tid >> 4, bn4 = tid & 15;     // B tile load: 16 k x 16 float4

    float acc[4][4] = {};

    for (int k0 = 0; k0 < K; k0 += 16) {
        __syncthreads();
        float4 av = *(const float4*)(A + (size_t)(m0 + arow) * K + k0 + ak4 * 4);
        As[ak4 * 4 + 0][arow] = av.x;
        As[ak4 * 4 + 1][arow] = av.y;
        As[ak4 * 4 + 2][arow] = av.z;
        As[ak4 * 4 + 3][arow] = av.w;
        float4 bv = *(const float4*)(Bw + (size_t)(k0 + bk) * N + n0 + bn4 * 4);
        *(float4*)&Bs[bk][bn4 * 4] = bv;
        __syncthreads();
#pragma unroll
        for (int k = 0; k < 16; k++) {
            float4 aa = *(const float4*)&As[k][tm];
            float4 bb = *(const float4*)&Bs[k][tn];
            float a4[4] = {aa.x, aa.y, aa.z, aa.w};
            float b4[4] = {bb.x, bb.y, bb.z, bb.w};
#pragma unroll
            for (int i = 0; i < 4; i++)
#pragma unroll
                for (int j = 0; j < 4; j++)
                    acc[i][j] = fmaf(a4[i], b4[j], acc[i][j]);
        }
    }

    float4 bv = *(const float4*)(bias + n0 + tn);
    float bias4[4] = {bv.x, bv.y, bv.z, bv.w};
#pragma unroll
    for (int i = 0; i < 4; i++) {
        size_t base = (size_t)(m0 + tm + i) * N + n0 + tn;
        float v[4];
#pragma unroll
        for (int j = 0; j < 4; j++) {
            float u = acc[i][j] + bias4[j];
            if (EPI == EPI_RELU) u = fmaxf(u, 0.0f);
            if (EPI == EPI_GELU) u = 0.5f * u * (1.0f + erff(u * 0.70710678118654752f));
            v[j] = u;
        }
        if (EPI == EPI_RES) {
            float4 rr = *(const float4*)(res + base);
            v[0] += rr.x; v[1] += rr.y; v[2] += rr.z; v[3] += rr.w;
        }
        float4 ov = {v[0], v[1], v[2], v[3]};
        *(float4*)(C + base) = ov;
    }
}

// ---------------------------------------------------------------------------
// Importance scores: warp per token, score = sigmoid(h . w2 + b2)
// ---------------------------------------------------------------------------
__global__ void score_kernel(const float* __restrict__ h,
                             const float* __restrict__ w2,
                             const float* __restrict__ b2,
                             float* __restrict__ scores) {
    int t = blockIdx.x * 8 + (threadIdx.x >> 5);
    int lane = threadIdx.x & 31;
    const float* hp = h + (size_t)t * DMODEL;
    float s = 0.f;
#pragma unroll
    for (int i = 0; i < 8; i++) s = fmaf(hp[lane + 32 * i], w2[lane + 32 * i], s);
#pragma unroll
    for (int o = 16; o > 0; o >>= 1) s += __shfl_xor_sync(0xffffffffu, s, o);
    if (lane == 0) scores[t] = 1.0f / (1.0f + __expf(-(s + b2[0])));
}

// ---------------------------------------------------------------------------
// Bottom-k mask via exact rank (ties broken by lower index, matching top_k)
// ---------------------------------------------------------------------------
__global__ void mask_kernel(const float* __restrict__ scores, int* __restrict__ mask) {
    __shared__ float ss[NTOK];
    int b = blockIdx.x / 9;
    int i0 = (blockIdx.x % 9) * 256;
    for (int idx = threadIdx.x; idx < NTOK; idx += 256)
        ss[idx] = scores[b * NTOK + idx];
    __syncthreads();
    int i = i0 + threadIdx.x;
    float si = ss[i];
    int cnt = 0;
    for (int j = 0; j < NTOK; j++) {
        float sj = ss[j];
        cnt += (sj < si) || (sj == si && j < i);
    }
    mask[b * NTOK + i] = (cnt < KDROP) ? 1 : 0;
}

// ---------------------------------------------------------------------------
// LayerNorm: warp per token (exact two-pass like the reference)
// ---------------------------------------------------------------------------
__global__ void ln_kernel(const float* __restrict__ x,
                          const float* __restrict__ g,
                          const float* __restrict__ bta,
                          float* __restrict__ y) {
    int t = blockIdx.x * 8 + (threadIdx.x >> 5);
    int lane = threadIdx.x & 31;
    const float* xp = x + (size_t)t * DMODEL;
    float v[8];
    float s = 0.f;
#pragma unroll
    for (int i = 0; i < 8; i++) { v[i] = xp[lane + 32 * i]; s += v[i]; }
#pragma unroll
    for (int o = 16; o > 0; o >>= 1) s += __shfl_xor_sync(0xffffffffu, s, o);
    float m = s * (1.0f / DMODEL);
    float vs = 0.f;
#pragma unroll
    for (int i = 0; i < 8; i++) { float d = v[i] - m; vs = fmaf(d, d, vs); }
#pragma unroll
    for (int o = 16; o > 0; o >>= 1) vs += __shfl_xor_sync(0xffffffffu, vs, o);
    float rs = rsqrtf(vs * (1.0f / DMODEL) + 1e-5f);
    float* yp = y + (size_t)t * DMODEL;
#pragma unroll
    for (int i = 0; i < 8; i++) {
        int d = lane + 32 * i;
        yp[d] = (v[i] - m) * rs * g[d] + bta[d];
    }
}

// ---------------------------------------------------------------------------
// Flash-style attention: block = (64 queries, one head, one batch).
// Keys streamed in 64-chunks with online softmax. Masked keys -> -1e30.
// ---------------------------------------------------------------------------
__global__ void attn_kernel(const float* __restrict__ qkv,
                            const int* __restrict__ mask,
                            float* __restrict__ out) {
    int b = blockIdx.z, h = blockIdx.y;
    int q0 = blockIdx.x * 64;
    int tid = threadIdx.x;

    __shared__ float Qs[32][68];
    __shared__ float Ks[32][68];
    __shared__ float Vs[64][36];
    __shared__ float Ss[64][68];
    __shared__ float row_m[64], row_l[64], row_alpha[64];
    __shared__ int   msk[64];

    const float* qb = qkv + (size_t)b * NTOK * (3 * DMODEL);
    int hoff = h * DK;

    // Load Q (transposed, k-major)
    for (int idx = tid; idx < 512; idx += 256) {
        int r = idx >> 3, k4 = idx & 7;
        float4 v = *(const float4*)(qb + (size_t)(q0 + r) * 768 + hoff + k4 * 4);
        Qs[k4 * 4 + 0][r] = v.x;
        Qs[k4 * 4 + 1][r] = v.y;
        Qs[k4 * 4 + 2][r] = v.z;
        Qs[k4 * 4 + 3][r] = v.w;
    }
    if (tid < 64) { row_m[tid] = -1e30f; row_l[tid] = 0.0f; }

    int rg = tid >> 4, cg = tid & 15;    // S microtile + PV mapping
    int sr = tid >> 2, sc = tid & 3;     // softmax mapping
    float o[4][2] = {};

    const float scale = 0.17677669529663687f;  // 1/sqrt(32)

    for (int c0 = 0; c0 < NTOK; c0 += 64) {
        __syncthreads();
        for (int idx = tid; idx < 512; idx += 256) {
            int r = idx >> 3, k4 = idx & 7;
            float4 kv = *(const float4*)(qb + (size_t)(c0 + r) * 768 + 256 + hoff + k4 * 4);
            Ks[k4 * 4 + 0][r] = kv.x;
            Ks[k4 * 4 + 1][r] = kv.y;
            Ks[k4 * 4 + 2][r] = kv.z;
            Ks[k4 * 4 + 3][r] = kv.w;
            float4 vv = *(const float4*)(qb + (size_t)(c0 + r) * 768 + 512 + hoff + k4 * 4);
            *(float4*)&Vs[r][k4 * 4] = vv;
        }
        if (tid < 64) msk[tid] = mask[b * NTOK + c0 + tid];
        __syncthreads();

        // S = Q K^T (4x4 microtile per thread)
        float acc[4][4] = {};
#pragma unroll
        for (int k = 0; k < 32; k++) {
            float4 aa = *(const float4*)&Qs[k][rg * 4];
            float4 bb = *(const float4*)&Ks[k][cg * 4];
            float a4[4] = {aa.x, aa.y, aa.z, aa.w};
            float b4[4] = {bb.x, bb.y, bb.z, bb.w};
#pragma unroll
            for (int i = 0; i < 4; i++)
#pragma unroll
                for (int j = 0; j < 4; j++)
                    acc[i][j] = fmaf(a4[i], b4[j], acc[i][j]);
        }
#pragma unroll
        for (int j = 0; j < 4; j++) {
            int jj = cg * 4 + j;
            bool md = (msk[jj] != 0);
#pragma unroll
            for (int i = 0; i < 4; i++)
                Ss[rg * 4 + i][jj] = md ? -1e30f : acc[i][j] * scale;
        }
        __syncthreads();

        // Online softmax (4 threads per row)
        float sv[16];
        float mloc = -1e30f;
#pragma unroll
        for (int t2 = 0; t2 < 16; t2++) {
            sv[t2] = Ss[sr][sc + 4 * t2];
            mloc = fmaxf(mloc, sv[t2]);
        }
        mloc = fmaxf(mloc, __shfl_xor_sync(0xffffffffu, mloc, 1));
        mloc = fmaxf(mloc, __shfl_xor_sync(0xffffffffu, mloc, 2));
        float mold = row_m[sr];
        float mnew = fmaxf(mold, mloc);
        float lsum = 0.f;
#pragma unroll
        for (int t2 = 0; t2 < 16; t2++) {
            float p = __expf(sv[t2] - mnew);
            Ss[sr][sc + 4 * t2] = p;
            lsum += p;
        }
        lsum += __shfl_xor_sync(0xffffffffu, lsum, 1);
        lsum += __shfl_xor_sync(0xffffffffu, lsum, 2);
        if (sc == 0) {
            float alpha = __expf(mold - mnew);
            row_l[sr] = row_l[sr] * alpha + lsum;
            row_m[sr] = mnew;
            row_alpha[sr] = alpha;
        }
        __syncthreads();

        // O = O*alpha + P @ V   (thread: 4 rows x 2 dims; dims at cg*2)
#pragma unroll
        for (int i = 0; i < 4; i++) {
            float a = row_alpha[rg * 4 + i];
            o[i][0] *= a;
            o[i][1] *= a;
        }
#pragma unroll 4
        for (int j = 0; j < 64; j += 2) {
            float2 v0 = *(const float2*)&Vs[j][cg * 2];
            float2 v1 = *(const float2*)&Vs[j + 1][cg * 2];
#pragma unroll
            for (int i = 0; i < 4; i++) {
                float2 pp = *(const float2*)&Ss[rg * 4 + i][j];
                o[i][0] = fmaf(pp.x, v0.x, fmaf(pp.y, v1.x, o[i][0]));
                o[i][1] = fmaf(pp.x, v0.y, fmaf(pp.y, v1.y, o[i][1]));
            }
        }
    }
    __syncthreads();

#pragma unroll
    for (int i = 0; i < 4; i++) {
        int r = rg * 4 + i;
        float inv = 1.0f / row_l[r];
        float2 res;
        res.x = o[i][0] * inv;
        res.y = o[i][1] * inv;
        *(float2*)(out + (size_t)(b * NTOK + q0 + r) * DMODEL + hoff + cg * 2) = res;
    }
}

// ---------------------------------------------------------------------------
// Final mean over tokens (no atomics -> bit deterministic)
// ---------------------------------------------------------------------------
__global__ void mean_kernel(const float* __restrict__ hln, float* __restrict__ out) {
    int b = blockIdx.x;
    int d = threadIdx.x;
    const float* p = hln + (size_t)b * NTOK * DMODEL + d;
    float s = 0.f;
#pragma unroll 8
    for (int n = 0; n < NTOK; n++) s += p[(size_t)n * DMODEL];
    out[b * DMODEL + d] = s * (1.0f / NTOK);
}

// ---------------------------------------------------------------------------
// Launcher
// ---------------------------------------------------------------------------
extern "C" void kernel_launch(void* const* d_in, const int* in_sizes, int n_in,
                              void* d_out, int out_size) {
    const float* x       = (const float*)d_in[0];
    const float* patch_w = (const float*)d_in[1];
    const float* patch_b = (const float*)d_in[2];
    const float* pos     = (const float*)d_in[3];
    const float* imp_w1  = (const float*)d_in[4];
    const float* imp_b1  = (const float*)d_in[5];
    const float* imp_w2  = (const float*)d_in[6];
    const float* imp_b2  = (const float*)d_in[7];
    const float* ln1_g   = (const float*)d_in[8];
    const float* ln1_b   = (const float*)d_in[9];
    const float* qkv_w   = (const float*)d_in[10];
    const float* qkv_b   = (const float*)d_in[11];
    const float* proj_w  = (const float*)d_in[12];
    const float* proj_b  = (const float*)d_in[13];
    const float* ln2_g   = (const float*)d_in[14];
    const float* ln2_b   = (const float*)d_in[15];
    const float* mlp_w1  = (const float*)d_in[16];
    const float* mlp_b1  = (const float*)d_in[17];
    const float* mlp_w2  = (const float*)d_in[18];
    const float* mlp_b2  = (const float*)d_in[19];
    const float* out_g   = (const float*)d_in[20];
    const float* out_b   = (const float*)d_in[21];
    float* out = (float*)d_out;

    float *tokens, *hln, *qkv, *attn, *mlp, *scores;
    int* mask;
    cudaGetSymbolAddress((void**)&tokens, g_tokens);
    cudaGetSymbolAddress((void**)&hln,    g_hln);
    cudaGetSymbolAddress((void**)&qkv,    g_qkv);
    cudaGetSymbolAddress((void**)&attn,   g_attn);
    cudaGetSymbolAddress((void**)&mlp,    g_mlp);
    cudaGetSymbolAddress((void**)&scores, g_scores);
    cudaGetSymbolAddress((void**)&mask,   g_mask);

    // 1) Patch embed + pos
    patch_kernel<<<MTOT, 256>>>(x, patch_w, patch_b, pos, tokens);

    // 2) Importance MLP -> scores -> bottom-k mask
    gemm_kernel<EPI_RELU><<<dim3(DMODEL / 64, MTOT / 64), 256>>>(
        tokens, imp_w1, imp_b1, nullptr, hln, MTOT, DMODEL, DMODEL);
    score_kernel<<<MTOT / 8, 256>>>(hln, imp_w2, imp_b2, scores);
    mask_kernel<<<BATCH * 9, 256>>>(scores, mask);

    // 3) Transformer layers
    for (int l = 0; l < DEPTH; l++) {
        ln_kernel<<<MTOT / 8, 256>>>(tokens, ln1_g + l * DMODEL, ln1_b + l * DMODEL, hln);
        gemm_kernel<EPI_BIAS><<<dim3(768 / 64, MTOT / 64), 256>>>(
            hln, qkv_w + (size_t)l * DMODEL * 768, qkv_b + l * 768, nullptr, qkv,
            MTOT, 768, DMODEL);
        attn_kernel<<<dim3(NTOK / 64, NHEADS, BATCH), 256>>>(qkv, mask, attn);
        gemm_kernel<EPI_RES><<<dim3(DMODEL / 64, MTOT / 64), 256>>>(
            attn, proj_w + (size_t)l * DMODEL * DMODEL, proj_b + l * DMODEL, tokens,
            tokens, MTOT, DMODEL, DMODEL);
        ln_kernel<<<MTOT / 8, 256>>>(tokens, ln2_g + l * DMODEL, ln2_b + l * DMODEL, hln);
        gemm_kernel<EPI_GELU><<<dim3(1024 / 64, MTOT / 64), 256>>>(
            hln, mlp_w1 + (size_t)l * DMODEL * 1024, mlp_b1 + l * 1024, nullptr, mlp,
            MTOT, 1024, DMODEL);
        gemm_kernel<EPI_RES><<<dim3(DMODEL / 64, MTOT / 64), 256>>>(
            mlp, mlp_w2 + (size_t)l * 1024 * DMODEL, mlp_b2 + l * DMODEL, tokens,
            tokens, MTOT, DMODEL, 1024);
    }

    // 4) Final LN + mean over tokens
    ln_kernel<<<MTOT / 8, 256>>>(tokens, out_g, out_b, hln);
    mean_kernel<<<BATCH, 256>>>(hln, out);
}

// round 2
// speedup vs baseline: 2.4053x; 2.4053x over previous
#include <cuda_runtime.h>
#include <math.h>

// ---------------------------------------------------------------------------
// Problem constants
// ---------------------------------------------------------------------------
#define BATCH   4
#define NTOK    2304
#define DMODEL  256
#define NHEADS  8
#define DK      32
#define DEPTH   3
#define KDROP   345              // int(0.15 * 2304)
#define MTOT    (BATCH * NTOK)   // 9216
#define NCHUNK  36               // NTOK / 64

// ---------------------------------------------------------------------------
// Scratch
// ---------------------------------------------------------------------------
__device__ float g_tokens[MTOT * DMODEL];
__device__ float g_hln   [MTOT * DMODEL];
__device__ float g_qkv   [MTOT * 3 * DMODEL];
__device__ float g_attn  [MTOT * DMODEL];
__device__ float g_mlp   [MTOT * 4 * DMODEL];
__device__ float g_scores[MTOT];
__device__ int   g_mask  [MTOT];
__device__ float g_part  [BATCH * NCHUNK * DMODEL];

// ---------------------------------------------------------------------------
// tf32 helpers
// ---------------------------------------------------------------------------
__device__ __forceinline__ unsigned f2tf(float f) {
    unsigned r;
    asm("cvt.rna.tf32.f32 %0, %1;" : "=r"(r) : "f"(f));
    return r;
}

__device__ __forceinline__ void mma_tf32(float c[4],
                                         unsigned a0, unsigned a1, unsigned a2, unsigned a3,
                                         unsigned b0, unsigned b1) {
    asm volatile(
        "mma.sync.aligned.m16n8k8.row.col.f32.tf32.tf32.f32 "
        "{%0,%1,%2,%3}, {%4,%5,%6,%7}, {%8,%9}, {%0,%1,%2,%3};"
        : "+f"(c[0]), "+f"(c[1]), "+f"(c[2]), "+f"(c[3])
        : "r"(a0), "r"(a1), "r"(a2), "r"(a3), "r"(b0), "r"(b1));
}

// ---------------------------------------------------------------------------
// Patch embed
// ---------------------------------------------------------------------------
__global__ void patch_kernel(const float* __restrict__ x,
                             const float* __restrict__ pw,
                             const float* __restrict__ pb,
                             const float* __restrict__ pos,
                             float* __restrict__ tokens) {
    int t = blockIdx.x;
    int b = t / NTOK, n = t % NTOK;
    int hc = n / 48, wc = n % 48;
    __shared__ float xs[12];
    if (threadIdx.x < 12) {
        int c = threadIdx.x / 4, pq = threadIdx.x % 4;
        int p = pq / 2, q = pq % 2;
        xs[threadIdx.x] = x[(((size_t)b * 3 + c) * 96 + (hc * 2 + p)) * 96 + (wc * 2 + q)];
    }
    __syncthreads();
    int d = threadIdx.x;
    float acc = pb[d];
#pragma unroll
    for (int e = 0; e < 12; e++) acc = fmaf(xs[e], pw[d * 12 + e], acc);
    tokens[(size_t)t * DMODEL + d] = acc + pos[(size_t)n * DMODEL + d];
}

// ---------------------------------------------------------------------------
// fp32 FFMA GEMM (kept ONLY for the importance MLP: mask path must be exact)
// 64x64 tile, BK=16, 256 threads, relu epilogue.
// ---------------------------------------------------------------------------
__global__ void gemm_f32_relu(const float* __restrict__ A,
                              const float* __restrict__ Bw,
                              const float* __restrict__ bias,
                              float* __restrict__ C,
                              int M, int N, int K) {
    __shared__ float As[16][68];
    __shared__ float Bs[16][68];
    int m0 = blockIdx.y * 64, n0 = blockIdx.x * 64;
    int tid = threadIdx.x;
    int tm = (tid >> 4) * 4, tn = (tid & 15) * 4;
    int arow = tid >> 2, ak4 = tid & 3;
    int bk = tid >> 4, bn4 = tid & 15;

    float acc[4][4] = {};
    for (int k0 = 0; k0 < K; k0 += 16) {
        __syncthreads();
        float4 av = *(const float4*)(A + (size_t)(m0 + arow) * K + k0 + ak4 * 4);
        As[ak4 * 4 + 0][arow] = av.x;
        As[ak4 * 4 + 1][arow] = av.y;
        As[ak4 * 4 + 2][arow] = av.z;
        As[ak4 * 4 + 3][arow] = av.w;
        float4 bv = *(const float4*)(Bw + (size_t)(k0 + bk) * N + n0 + bn4 * 4);
        *(float4*)&Bs[bk][bn4 * 4] = bv;
        __syncthreads();
#pragma unroll
        for (int k = 0; k < 16; k++) {
            float4 aa = *(const float4*)&As[k][tm];
            float4 bb = *(const float4*)&Bs[k][tn];
            float a4[4] = {aa.x, aa.y, aa.z, aa.w};
            float b4[4] = {bb.x, bb.y, bb.z, bb.w};
#pragma unroll
            for (int i = 0; i < 4; i++)
#pragma unroll
                for (int j = 0; j < 4; j++)
                    acc[i][j] = fmaf(a4[i], b4[j], acc[i][j]);
        }
    }
    float4 bv = *(const float4*)(bias + n0 + tn);
    float bias4[4] = {bv.x, bv.y, bv.z, bv.w};
#pragma unroll
    for (int i = 0; i < 4; i++) {
        size_t base = (size_t)(m0 + tm + i) * N + n0 + tn;
        float4 ov;
        ov.x = fmaxf(acc[i][0] + bias4[0], 0.f);
        ov.y = fmaxf(acc[i][1] + bias4[1], 0.f);
        ov.z = fmaxf(acc[i][2] + bias4[2], 0.f);
        ov.w = fmaxf(acc[i][3] + bias4[3], 0.f);
        *(float4*)(C + base) = ov;
    }
}

// ---------------------------------------------------------------------------
// TF32 tensor-core GEMM: C[M,N] = A[M,K] @ B[K,N] (+bias, epilogue).
// Block tile 128x128, BK=32, 256 threads = 8 warps (2x4), warp tile 64x32.
// Conflict-free smem (stride 136 words).
// ---------------------------------------------------------------------------
enum { EPI_BIAS = 0, EPI_GELU = 2, EPI_RES = 3 };

template <int EPI>
__global__ __launch_bounds__(256) void gemm_tf32(const float* __restrict__ A,
                                                 const float* __restrict__ Bw,
                                                 const float* __restrict__ bias,
                                                 const float* res,
                                                 float* C,
                                                 int M, int N, int K) {
    __shared__ unsigned As[32][136];   // [k][m]
    __shared__ unsigned Bs[32][136];   // [k][n]

    int m0 = blockIdx.y * 128, n0 = blockIdx.x * 128;
    int tid = threadIdx.x;
    int warp = tid >> 5, lane = tid & 31;
    int tq = lane >> 2, tc = lane & 3;
    int mb = (warp >> 2) * 64;         // 0 or 64
    int nb = (warp & 3) * 32;          // 0..96

    // global load mapping
    int arow = tid >> 1, ahalf = (tid & 1) * 16;
    int bkr = tid >> 3, bc = (tid & 7) * 4;

    float acc[4][4][4] = {};

    for (int k0 = 0; k0 < K; k0 += 32) {
        __syncthreads();
        const float* ap = A + (size_t)(m0 + arow) * K + k0 + ahalf;
#pragma unroll
        for (int i = 0; i < 4; i++) {
            float4 v = *(const float4*)(ap + i * 4);
            As[ahalf + i * 4 + 0][arow] = f2tf(v.x);
            As[ahalf + i * 4 + 1][arow] = f2tf(v.y);
            As[ahalf + i * 4 + 2][arow] = f2tf(v.z);
            As[ahalf + i * 4 + 3][arow] = f2tf(v.w);
        }
        const float* bp = Bw + (size_t)(k0 + bkr) * N + n0;
#pragma unroll
        for (int i = 0; i < 4; i++) {
            int col = bc + i * 32;
            float4 v = *(const float4*)(bp + col);
            Bs[bkr][col + 0] = f2tf(v.x);
            Bs[bkr][col + 1] = f2tf(v.y);
            Bs[bkr][col + 2] = f2tf(v.z);
            Bs[bkr][col + 3] = f2tf(v.w);
        }
        __syncthreads();

#pragma unroll
        for (int ks = 0; ks < 4; ks++) {
            int kk = ks * 8;
            unsigned a[4][4], b[4][2];
#pragma unroll
            for (int mt = 0; mt < 4; mt++) {
                int m = mb + 16 * mt + tq;
                a[mt][0] = As[kk + tc][m];
                a[mt][1] = As[kk + tc][m + 8];
                a[mt][2] = As[kk + tc + 4][m];
                a[mt][3] = As[kk + tc + 4][m + 8];
            }
#pragma unroll
            for (int nt = 0; nt < 4; nt++) {
                int n = nb + 8 * nt + tq;
                b[nt][0] = Bs[kk + tc][n];
                b[nt][1] = Bs[kk + tc + 4][n];
            }
#pragma unroll
            for (int mt = 0; mt < 4; mt++)
#pragma unroll
                for (int nt = 0; nt < 4; nt++)
                    mma_tf32(acc[mt][nt], a[mt][0], a[mt][1], a[mt][2], a[mt][3],
                             b[nt][0], b[nt][1]);
        }
    }

    // epilogue
#pragma unroll
    for (int mt = 0; mt < 4; mt++) {
#pragma unroll
        for (int nt = 0; nt < 4; nt++) {
            int col = n0 + nb + 8 * nt + 2 * tc;
            float2 bb = *(const float2*)(bias + col);
#pragma unroll
            for (int half = 0; half < 2; half++) {
                int row = m0 + mb + 16 * mt + tq + half * 8;
                float u0 = acc[mt][nt][half * 2 + 0] + bb.x;
                float u1 = acc[mt][nt][half * 2 + 1] + bb.y;
                if (EPI == EPI_GELU) {
                    u0 = 0.5f * u0 * (1.0f + erff(u0 * 0.70710678118654752f));
                    u1 = 0.5f * u1 * (1.0f + erff(u1 * 0.70710678118654752f));
                }
                size_t base = (size_t)row * N + col;
                if (EPI == EPI_RES) {
                    float2 rr = *(const float2*)(res + base);
                    u0 += rr.x;
                    u1 += rr.y;
                }
                float2 ov = {u0, u1};
                *(float2*)(C + base) = ov;
            }
        }
    }
}

// ---------------------------------------------------------------------------
// Importance scores
// ---------------------------------------------------------------------------
__global__ void score_kernel(const float* __restrict__ h,
                             const float* __restrict__ w2,
                             const float* __restrict__ b2,
                             float* __restrict__ scores) {
    int t = blockIdx.x * 8 + (threadIdx.x >> 5);
    int lane = threadIdx.x & 31;
    const float* hp = h + (size_t)t * DMODEL;
    float s = 0.f;
#pragma unroll
    for (int i = 0; i < 8; i++) s = fmaf(hp[lane + 32 * i], w2[lane + 32 * i], s);
#pragma unroll
    for (int o = 16; o > 0; o >>= 1) s += __shfl_xor_sync(0xffffffffu, s, o);
    if (lane == 0) scores[t] = 1.0f / (1.0f + __expf(-(s + b2[0])));
}

// ---------------------------------------------------------------------------
// Bottom-k mask via exact rank
// ---------------------------------------------------------------------------
__global__ void mask_kernel(const float* __restrict__ scores, int* __restrict__ mask) {
    __shared__ float ss[NTOK];
    int b = blockIdx.x / 9;
    int i0 = (blockIdx.x % 9) * 256;
    for (int idx = threadIdx.x; idx < NTOK; idx += 256)
        ss[idx] = scores[b * NTOK + idx];
    __syncthreads();
    int i = i0 + threadIdx.x;
    float si = ss[i];
    int cnt = 0;
    for (int j = 0; j < NTOK; j++) {
        float sj = ss[j];
        cnt += (sj < si) || (sj == si && j < i);
    }
    mask[b * NTOK + i] = (cnt < KDROP) ? 1 : 0;
}

// ---------------------------------------------------------------------------
// LayerNorm (warp/token, exact two-pass)
// ---------------------------------------------------------------------------
__global__ void ln_kernel(const float* __restrict__ x,
                          const float* __restrict__ g,
                          const float* __restrict__ bta,
                          float* __restrict__ y) {
    int t = blockIdx.x * 8 + (threadIdx.x >> 5);
    int lane = threadIdx.x & 31;
    const float* xp = x + (size_t)t * DMODEL;
    float v[8];
    float s = 0.f;
#pragma unroll
    for (int i = 0; i < 8; i++) { v[i] = xp[lane + 32 * i]; s += v[i]; }
#pragma unroll
    for (int o = 16; o > 0; o >>= 1) s += __shfl_xor_sync(0xffffffffu, s, o);
    float m = s * (1.0f / DMODEL);
    float vs = 0.f;
#pragma unroll
    for (int i = 0; i < 8; i++) { float d = v[i] - m; vs = fmaf(d, d, vs); }
#pragma unroll
    for (int o = 16; o > 0; o >>= 1) vs += __shfl_xor_sync(0xffffffffu, vs, o);
    float rs = rsqrtf(vs * (1.0f / DMODEL) + 1e-5f);
    float* yp = y + (size_t)t * DMODEL;
#pragma unroll
    for (int i = 0; i < 8; i++) {
        int d = lane + 32 * i;
        yp[d] = (v[i] - m) * rs * g[d] + bta[d];
    }
}

// ---------------------------------------------------------------------------
// TF32 flash attention: block = 64 queries x 1 head. 128 threads, 4 warps;
// each warp owns 16 query rows exclusively (register-held softmax state).
// ---------------------------------------------------------------------------
__global__ __launch_bounds__(128) void attn_tf32(const float* __restrict__ qkv,
                                                 const int* __restrict__ mask,
                                                 float* __restrict__ out) {
    __shared__ unsigned Qs[64][36];
    __shared__ unsigned Ks[64][36];
    __shared__ unsigned Vs[64][36];
    __shared__ unsigned Ps[4][16][68];
    __shared__ float    mskf[64];

    int b = blockIdx.z, h = blockIdx.y;
    int q0 = blockIdx.x * 64;
    int tid = threadIdx.x;
    int w = tid >> 5, lane = tid & 31;
    int tq = lane >> 2, tc = lane & 3;
    int hoff = h * DK;

    const float* qb = qkv + (size_t)b * NTOK * 768;

    // Load Q tile -> shared (tf32)
    {
        int r = tid >> 1, kbase = (tid & 1) * 16;
        const float* qp = qb + (size_t)(q0 + r) * 768 + hoff + kbase;
#pragma unroll
        for (int i = 0; i < 4; i++) {
            float4 v = *(const float4*)(qp + i * 4);
            Qs[r][kbase + i * 4 + 0] = f2tf(v.x);
            Qs[r][kbase + i * 4 + 1] = f2tf(v.y);
            Qs[r][kbase + i * 4 + 2] = f2tf(v.z);
            Qs[r][kbase + i * 4 + 3] = f2tf(v.w);
        }
    }
    __syncthreads();

    // Q fragments resident in registers
    unsigned qa[4][4];
#pragma unroll
    for (int ks = 0; ks < 4; ks++) {
        int row = w * 16 + tq, col = ks * 8 + tc;
        qa[ks][0] = Qs[row][col];
        qa[ks][1] = Qs[row + 8][col];
        qa[ks][2] = Qs[row][col + 4];
        qa[ks][3] = Qs[row + 8][col + 4];
    }

    float m0r = -1e30f, m1r = -1e30f, l0 = 0.f, l1 = 0.f;
    float oacc[4][4] = {};
    const float scale = 0.17677669529663687f;

    for (int c0 = 0; c0 < NTOK; c0 += 64) {
        __syncthreads();
        {
            int r = tid >> 1, kbase = (tid & 1) * 16;
            const float* kp = qb + (size_t)(c0 + r) * 768 + 256 + hoff + kbase;
            const float* vp = qb + (size_t)(c0 + r) * 768 + 512 + hoff + kbase;
#pragma unroll
            for (int i = 0; i < 4; i++) {
                float4 kv = *(const float4*)(kp + i * 4);
                Ks[r][kbase + i * 4 + 0] = f2tf(kv.x);
                Ks[r][kbase + i * 4 + 1] = f2tf(kv.y);
                Ks[r][kbase + i * 4 + 2] = f2tf(kv.z);
                Ks[r][kbase + i * 4 + 3] = f2tf(kv.w);
                float4 vv = *(const float4*)(vp + i * 4);
                Vs[r][kbase + i * 4 + 0] = f2tf(vv.x);
                Vs[r][kbase + i * 4 + 1] = f2tf(vv.y);
                Vs[r][kbase + i * 4 + 2] = f2tf(vv.z);
                Vs[r][kbase + i * 4 + 3] = f2tf(vv.w);
            }
            if (tid < 64) mskf[tid] = mask[b * NTOK + c0 + tid] ? -1e30f : 0.f;
        }
        __syncthreads();

        // S = Q K^T  (warp: 16 rows x 64 cols)
        float sacc[8][4] = {};
#pragma unroll
        for (int ks = 0; ks < 4; ks++) {
            int kk = ks * 8;
#pragma unroll
            for (int nt = 0; nt < 8; nt++) {
                unsigned b0 = Ks[8 * nt + tq][kk + tc];
                unsigned b1 = Ks[8 * nt + tq][kk + tc + 4];
                mma_tf32(sacc[nt], qa[ks][0], qa[ks][1], qa[ks][2], qa[ks][3], b0, b1);
            }
        }

        // scale + mask, row max
        float mx0 = -1e30f, mx1 = -1e30f;
#pragma unroll
        for (int nt = 0; nt < 8; nt++) {
            float2 mb = *(const float2*)&mskf[8 * nt + 2 * tc];
            sacc[nt][0] = sacc[nt][0] * scale + mb.x;
            sacc[nt][1] = sacc[nt][1] * scale + mb.y;
            sacc[nt][2] = sacc[nt][2] * scale + mb.x;
            sacc[nt][3] = sacc[nt][3] * scale + mb.y;
            mx0 = fmaxf(mx0, fmaxf(sacc[nt][0], sacc[nt][1]));
            mx1 = fmaxf(mx1, fmaxf(sacc[nt][2], sacc[nt][3]));
        }
        mx0 = fmaxf(mx0, __shfl_xor_sync(0xffffffffu, mx0, 1));
        mx0 = fmaxf(mx0, __shfl_xor_sync(0xffffffffu, mx0, 2));
        mx1 = fmaxf(mx1, __shfl_xor_sync(0xffffffffu, mx1, 1));
        mx1 = fmaxf(mx1, __shfl_xor_sync(0xffffffffu, mx1, 2));

        float mn0 = fmaxf(m0r, mx0), mn1 = fmaxf(m1r, mx1);
        float a0 = __expf(m0r - mn0), a1 = __expf(m1r - mn1);
        m0r = mn0; m1r = mn1;

        float ps0 = 0.f, ps1 = 0.f;
#pragma unroll
        for (int nt = 0; nt < 8; nt++) {
            float p00 = __expf(sacc[nt][0] - mn0);
            float p01 = __expf(sacc[nt][1] - mn0);
            float p10 = __expf(sacc[nt][2] - mn1);
            float p11 = __expf(sacc[nt][3] - mn1);
            ps0 += p00 + p01;
            ps1 += p10 + p11;
            int col = 8 * nt + 2 * tc;
            Ps[w][tq][col] = f2tf(p00);
            Ps[w][tq][col + 1] = f2tf(p01);
            Ps[w][tq + 8][col] = f2tf(p10);
            Ps[w][tq + 8][col + 1] = f2tf(p11);
        }
        ps0 += __shfl_xor_sync(0xffffffffu, ps0, 1);
        ps0 += __shfl_xor_sync(0xffffffffu, ps0, 2);
        ps1 += __shfl_xor_sync(0xffffffffu, ps1, 1);
        ps1 += __shfl_xor_sync(0xffffffffu, ps1, 2);
        l0 = l0 * a0 + ps0;
        l1 = l1 * a1 + ps1;

#pragma unroll
        for (int nt = 0; nt < 4; nt++) {
            oacc[nt][0] *= a0; oacc[nt][1] *= a0;
            oacc[nt][2] *= a1; oacc[nt][3] *= a1;
        }
        __syncwarp();

        // O += P @ V  (warp: 16 rows x 32 dims)
#pragma unroll
        for (int ks = 0; ks < 8; ks++) {
            int kk = ks * 8;
            unsigned pa0 = Ps[w][tq][kk + tc];
            unsigned pa1 = Ps[w][tq + 8][kk + tc];
            unsigned pa2 = Ps[w][tq][kk + tc + 4];
            unsigned pa3 = Ps[w][tq + 8][kk + tc + 4];
#pragma unroll
            for (int nt = 0; nt < 4; nt++) {
                unsigned b0 = Vs[kk + tc][8 * nt + tq];
                unsigned b1 = Vs[kk + tc + 4][8 * nt + tq];
                mma_tf32(oacc[nt], pa0, pa1, pa2, pa3, b0, b1);
            }
        }
        __syncwarp();
    }

    float inv0 = 1.0f / l0, inv1 = 1.0f / l1;
    int r0 = b * NTOK + q0 + w * 16 + tq;
#pragma unroll
    for (int nt = 0; nt < 4; nt++) {
        int col = hoff + 8 * nt + 2 * tc;
        float2 v0 = {oacc[nt][0] * inv0, oacc[nt][1] * inv0};
        float2 v1 = {oacc[nt][2] * inv1, oacc[nt][3] * inv1};
        *(float2*)(out + (size_t)r0 * DMODEL + col) = v0;
        *(float2*)(out + (size_t)(r0 + 8) * DMODEL + col) = v1;
    }
}

// ---------------------------------------------------------------------------
// 2-stage mean over tokens
// ---------------------------------------------------------------------------
__global__ void mean1_kernel(const float* __restrict__ hln, float* __restrict__ part) {
    int b = blockIdx.y, ch = blockIdx.x, d = threadIdx.x;
    const float* p = hln + ((size_t)b * NTOK + ch * 64) * DMODEL + d;
    float s = 0.f;
#pragma unroll 8
    for (int n = 0; n < 64; n++) s += p[(size_t)n * DMODEL];
    part[((size_t)b * NCHUNK + ch) * DMODEL + d] = s;
}

__global__ void mean2_kernel(const float* __restrict__ part, float* __restrict__ out) {
    int b = blockIdx.x, d = threadIdx.x;
    float s = 0.f;
    for (int c = 0; c < NCHUNK; c++) s += part[((size_t)b * NCHUNK + c) * DMODEL + d];
    out[b * DMODEL + d] = s * (1.0f / NTOK);
}

// ---------------------------------------------------------------------------
// Launcher
// ---------------------------------------------------------------------------
extern "C" void kernel_launch(void* const* d_in, const int* in_sizes, int n_in,
                              void* d_out, int out_size) {
    const float* x       = (const float*)d_in[0];
    const float* patch_w = (const float*)d_in[1];
    const float* patch_b = (const float*)d_in[2];
    const float* pos     = (const float*)d_in[3];
    const float* imp_w1  = (const float*)d_in[4];
    const float* imp_b1  = (const float*)d_in[5];
    const float* imp_w2  = (const float*)d_in[6];
    const float* imp_b2  = (const float*)d_in[7];
    const float* ln1_g   = (const float*)d_in[8];
    const float* ln1_b   = (const float*)d_in[9];
    const float* qkv_w   = (const float*)d_in[10];
    const float* qkv_b   = (const float*)d_in[11];
    const float* proj_w  = (const float*)d_in[12];
    const float* proj_b  = (const float*)d_in[13];
    const float* ln2_g   = (const float*)d_in[14];
    const float* ln2_b   = (const float*)d_in[15];
    const float* mlp_w1  = (const float*)d_in[16];
    const float* mlp_b1  = (const float*)d_in[17];
    const float* mlp_w2  = (const float*)d_in[18];
    const float* mlp_b2  = (const float*)d_in[19];
    const float* out_g   = (const float*)d_in[20];
    const float* out_b   = (const float*)d_in[21];
    float* out = (float*)d_out;

    float *tokens, *hln, *qkv, *attn, *mlp, *scores, *part;
    int* mask;
    cudaGetSymbolAddress((void**)&tokens, g_tokens);
    cudaGetSymbolAddress((void**)&hln,    g_hln);
    cudaGetSymbolAddress((void**)&qkv,    g_qkv);
    cudaGetSymbolAddress((void**)&attn,   g_attn);
    cudaGetSymbolAddress((void**)&mlp,    g_mlp);
    cudaGetSymbolAddress((void**)&scores, g_scores);
    cudaGetSymbolAddress((void**)&mask,   g_mask);
    cudaGetSymbolAddress((void**)&part,   g_part);

    // 1) Patch embed + pos
    patch_kernel<<<MTOT, 256>>>(x, patch_w, patch_b, pos, tokens);

    // 2) Importance MLP (exact fp32: feeds discrete top-k) -> scores -> mask
    gemm_f32_relu<<<dim3(DMODEL / 64, MTOT / 64), 256>>>(
        tokens, imp_w1, imp_b1, hln, MTOT, DMODEL, DMODEL);
    score_kernel<<<MTOT / 8, 256>>>(hln, imp_w2, imp_b2, scores);
    mask_kernel<<<BATCH * 9, 256>>>(scores, mask);

    // 3) Transformer layers (tf32 tensor cores)
    for (int l = 0; l < DEPTH; l++) {
        ln_kernel<<<MTOT / 8, 256>>>(tokens, ln1_g + l * DMODEL, ln1_b + l * DMODEL, hln);
        gemm_tf32<EPI_BIAS><<<dim3(768 / 128, MTOT / 128), 256>>>(
            hln, qkv_w + (size_t)l * DMODEL * 768, qkv_b + l * 768, nullptr, qkv,
            MTOT, 768, DMODEL);
        attn_tf32<<<dim3(NTOK / 64, NHEADS, BATCH), 128>>>(qkv, mask, attn);
        gemm_tf32<EPI_RES><<<dim3(DMODEL / 128, MTOT / 128), 256>>>(
            attn, proj_w + (size_t)l * DMODEL * DMODEL, proj_b + l * DMODEL, tokens,
            tokens, MTOT, DMODEL, DMODEL);
        ln_kernel<<<MTOT / 8, 256>>>(tokens, ln2_g + l * DMODEL, ln2_b + l * DMODEL, hln);
        gemm_tf32<EPI_GELU><<<dim3(1024 / 128, MTOT / 128), 256>>>(
            hln, mlp_w1 + (size_t)l * DMODEL * 1024, mlp_b1 + l * 1024, nullptr, mlp,
            MTOT, 1024, DMODEL);
        gemm_tf32<EPI_RES><<<dim3(DMODEL / 128, MTOT / 128), 256>>>(
            mlp, mlp_w2 + (size_t)l * 1024 * DMODEL, mlp_b2 + l * DMODEL, tokens,
            tokens, MTOT, DMODEL, 1024);
    }

    // 4) Final LN + mean
    ln_kernel<<<MTOT / 8, 256>>>(tokens, out_g, out_b, hln);
    mean1_kernel<<<dim3(NCHUNK, BATCH), 256>>>(hln, part);
    mean2_kernel<<<BATCH, 256>>>(part, out);
}